// round 8
// baseline (speedup 1.0000x reference)
#include <cuda_runtime.h>
#include <cuda_bf16.h>
#include <cstdint>

#define TOKENS 2048   // B*T
#define BATCH  4
#define SEQ    512
#define HID    2048
#define VOCAB  32000

#define BM 128
#define BN 128
#define BK 32
#define LDS_PAD 40    // halves per smem row (32 + 8 pad) -> conflict-free ldmatrix

// scratch (allocation-free rule: __device__ globals)
__device__ float g_sumexp[2 * TOKENS];
__device__ float g_tgt[2 * TOKENS];

// ---------------------------------------------------------------------------
__global__ void k_init() {
    int i = blockIdx.x * blockDim.x + threadIdx.x;
    if (i < 2 * TOKENS) g_sumexp[i] = 0.f;
}

// ---------------------------------------------------------------------------
// Target logits: one warp per (model, token). Dot(x[m], W[y[m]]) over H=2048.
__global__ void k_target(const float* __restrict__ x, const float* __restrict__ rx,
                         const float* __restrict__ W, const float* __restrict__ rW,
                         const int* __restrict__ y) {
    int warp = (blockIdx.x * blockDim.x + threadIdx.x) >> 5;
    int lane = threadIdx.x & 31;
    if (warp >= 2 * TOKENS) return;
    int model = warp >> 11;            // TOKENS = 2^11
    int m     = warp & (TOKENS - 1);

    // int64-vs-int32 detection: y[0]=y[1]=-100 guaranteed by reference masking.
    // int64 layout -> int32 view [1] is the high word of -100 == -1.
    bool y64  = (y[1] == -1);
    int label = y[y64 ? 2 * m : m];

    float v = 0.f;
    if (label >= 0) {
        const float4* a4 = (const float4*)((model ? rx : x) + (size_t)m * HID);
        const float4* b4 = (const float4*)((model ? rW : W) + (size_t)label * HID);
        #pragma unroll 4
        for (int i = lane; i < HID / 4; i += 32) {
            float4 av = a4[i], bv = b4[i];
            v += av.x * bv.x + av.y * bv.y + av.z * bv.z + av.w * bv.w;
        }
    }
    #pragma unroll
    for (int s = 16; s; s >>= 1) v += __shfl_xor_sync(0xffffffffu, v, s);
    if (lane == 0) g_tgt[warp] = v;
}

// ---------------------------------------------------------------------------
__device__ __forceinline__ void ldsm_x4(uint32_t& r0, uint32_t& r1, uint32_t& r2,
                                        uint32_t& r3, uint32_t addr) {
    asm volatile("ldmatrix.sync.aligned.m8n8.x4.shared.b16 {%0,%1,%2,%3}, [%4];\n"
                 : "=r"(r0), "=r"(r1), "=r"(r2), "=r"(r3) : "r"(addr));
}
__device__ __forceinline__ void ldsm_x2(uint32_t& r0, uint32_t& r1, uint32_t addr) {
    asm volatile("ldmatrix.sync.aligned.m8n8.x2.shared.b16 {%0,%1}, [%2];\n"
                 : "=r"(r0), "=r"(r1) : "r"(addr));
}
__device__ __forceinline__ void mma16816(float* c, const uint32_t* a, const uint32_t* b) {
    asm volatile(
        "mma.sync.aligned.m16n8k16.row.col.f32.bf16.bf16.f32 "
        "{%0,%1,%2,%3}, {%4,%5,%6,%7}, {%8,%9}, {%0,%1,%2,%3};\n"
        : "+f"(c[0]), "+f"(c[1]), "+f"(c[2]), "+f"(c[3])
        : "r"(a[0]), "r"(a[1]), "r"(a[2]), "r"(a[3]), "r"(b[0]), "r"(b[1]));
}
__device__ __forceinline__ uint2 pack_bf16x4(float4 v) {
    __nv_bfloat162 lo = __floats2bfloat162_rn(v.x, v.y);
    __nv_bfloat162 hi = __floats2bfloat162_rn(v.z, v.w);
    uint2 r;
    r.x = *(uint32_t*)&lo;
    r.y = *(uint32_t*)&hi;
    return r;
}

// GEMM + online exp-sum epilogue.
// grid = (M/BM fastest, N/BN, 2 models); 256 threads = 8 warps in 2(M)x4(N),
// each warp owns a 64x32 output tile via 4x4 m16n8k16 fragments.
__global__ __launch_bounds__(256)
void k_gemm(const float* __restrict__ x, const float* __restrict__ rx,
            const float* __restrict__ W, const float* __restrict__ rW) {
    const int model = blockIdx.z;
    const float* A = model ? rx : x;
    const float* B = model ? rW : W;
    const int bm = blockIdx.x;
    const int bn = blockIdx.y;

    __shared__ __nv_bfloat16 As[2][BM * LDS_PAD];
    __shared__ __nv_bfloat16 Bs[2][BN * LDS_PAD];

    const int tid  = threadIdx.x;
    const int lane = tid & 31;
    const int w    = tid >> 5;
    const int wm   = w >> 2;   // 0..1
    const int wn   = w & 3;    // 0..3

    // Global loads: thread t covers rows (t>>3)+j*32, float4 col (t&7).
    // Per j a warp reads 4 rows x 8 lanes x 16B = 4 fully-coalesced 128B lines.
    const int glr = tid >> 3;        // 0..31
    const int glc = tid & 7;         // float4 index in the 32-float K-chunk
    const float* Ag = A + (size_t)(bm * BM + glr) * HID + glc * 4;
    const float* Bg = B + (size_t)(bn * BN + glr) * HID + glc * 4;

    float acc[4][4][4];
    #pragma unroll
    for (int i = 0; i < 4; i++)
        #pragma unroll
        for (int j = 0; j < 4; j++)
            #pragma unroll
            for (int e = 0; e < 4; e++) acc[i][j][e] = 0.f;

    uint32_t asb[2], bsb[2];
    asb[0] = (uint32_t)__cvta_generic_to_shared(&As[0][0]);
    asb[1] = (uint32_t)__cvta_generic_to_shared(&As[1][0]);
    bsb[0] = (uint32_t)__cvta_generic_to_shared(&Bs[0][0]);
    bsb[1] = (uint32_t)__cvta_generic_to_shared(&Bs[1][0]);

    float4 ra[4], rb[4];
    #pragma unroll
    for (int j = 0; j < 4; j++) {
        ra[j] = *(const float4*)(Ag + (size_t)j * 32 * HID);
        rb[j] = *(const float4*)(Bg + (size_t)j * 32 * HID);
    }
    // stage tile 0 -> buffer 0
    #pragma unroll
    for (int j = 0; j < 4; j++) {
        *(uint2*)&As[0][(glr + j * 32) * LDS_PAD + glc * 4] = pack_bf16x4(ra[j]);
        *(uint2*)&Bs[0][(glr + j * 32) * LDS_PAD + glc * 4] = pack_bf16x4(rb[j]);
    }

    const int KIT = HID / BK;   // 64
    for (int it = 0; it < KIT; ++it) {
        __syncthreads();                       // staged buffer (it&1) visible
        const int buf = it & 1;

        if (it + 1 < KIT) {
            const int ko = (it + 1) * BK;
            #pragma unroll
            for (int j = 0; j < 4; j++) {
                ra[j] = *(const float4*)(Ag + (size_t)j * 32 * HID + ko);
                rb[j] = *(const float4*)(Bg + (size_t)j * 32 * HID + ko);
            }
        }

        #pragma unroll
        for (int ks = 0; ks < 2; ks++) {
            uint32_t af[4][4];
            #pragma unroll
            for (int mi = 0; mi < 4; mi++) {
                int row = wm * 64 + mi * 16 + ((lane >> 3) & 1) * 8 + (lane & 7);
                int col = ks * 16 + (lane >> 4) * 8;
                ldsm_x4(af[mi][0], af[mi][1], af[mi][2], af[mi][3],
                        asb[buf] + (uint32_t)(row * LDS_PAD + col) * 2);
            }
            uint32_t bfrag[4][2];
            #pragma unroll
            for (int ni = 0; ni < 4; ni++) {
                int row = wn * 32 + ni * 8 + (lane & 7);
                int col = ks * 16 + ((lane >> 3) & 1) * 8;
                ldsm_x2(bfrag[ni][0], bfrag[ni][1],
                        bsb[buf] + (uint32_t)(row * LDS_PAD + col) * 2);
            }
            #pragma unroll
            for (int mi = 0; mi < 4; mi++)
                #pragma unroll
                for (int ni = 0; ni < 4; ni++)
                    mma16816(acc[mi][ni], af[mi], bfrag[ni]);
        }

        __syncthreads();                       // everyone done with buf^1 reads
        if (it + 1 < KIT) {
            const int nb = (it + 1) & 1;
            #pragma unroll
            for (int j = 0; j < 4; j++) {
                *(uint2*)&As[nb][(glr + j * 32) * LDS_PAD + glc * 4] = pack_bf16x4(ra[j]);
                *(uint2*)&Bs[nb][(glr + j * 32) * LDS_PAD + glc * 4] = pack_bf16x4(rb[j]);
            }
        }
    }

    // Epilogue: exp + row-sum over this block's 128 vocab columns.
    // c0,c1 -> row lane>>2 ; c2,c3 -> row (lane>>2)+8 ; quad lanes share a row.
    const int rowbase = bm * BM + wm * 64;
    #pragma unroll
    for (int mi = 0; mi < 4; mi++) {
        float s0 = 0.f, s1 = 0.f;
        #pragma unroll
        for (int ni = 0; ni < 4; ni++) {
            s0 += __expf(acc[mi][ni][0]) + __expf(acc[mi][ni][1]);
            s1 += __expf(acc[mi][ni][2]) + __expf(acc[mi][ni][3]);
        }
        s0 += __shfl_xor_sync(0xffffffffu, s0, 1);
        s0 += __shfl_xor_sync(0xffffffffu, s0, 2);
        s1 += __shfl_xor_sync(0xffffffffu, s1, 1);
        s1 += __shfl_xor_sync(0xffffffffu, s1, 2);
        if ((lane & 3) == 0) {
            int r = rowbase + mi * 16 + (lane >> 2);
            atomicAdd(&g_sumexp[model * TOKENS + r],     s0);
            atomicAdd(&g_sumexp[model * TOKENS + r + 8], s1);
        }
    }
}

// ---------------------------------------------------------------------------
__global__ void k_final(const int* __restrict__ y,
                        const unsigned char* __restrict__ pl_raw,
                        float* __restrict__ out) {
    __shared__ float pol[BATCH], ref[BATCH], cnt[BATCH];
    int tid = threadIdx.x;
    if (tid < BATCH) { pol[tid] = 0.f; ref[tid] = 0.f; cnt[tid] = 0.f; }
    __syncthreads();

    bool y64 = (y[1] == -1);
    for (int m = tid; m < TOKENS; m += blockDim.x) {
        int label = y[y64 ? 2 * m : m];
        if (label >= 0) {
            int b = m / SEQ;
            float p = g_tgt[m]          - logf(g_sumexp[m]);
            float r = g_tgt[TOKENS + m] - logf(g_sumexp[TOKENS + m]);
            atomicAdd(&pol[b], p);
            atomicAdd(&ref[b], r);
            atomicAdd(&cnt[b], 1.f);
        }
    }
    __syncthreads();

    if (tid == 0) {
        // preference_labels dtype hedge: int32 / float32 / byte encodings.
        const uint32_t* pi = (const uint32_t*)pl_raw;
        uint32_t i0 = pi[0], i1 = pi[1], i2 = pi[2], i3 = pi[3];
        bool lab[BATCH];
        bool int_mode = (i0 <= 1u) && (i1 <= 1u) && (i2 <= 1u) && (i3 <= 1u);
        bool flt_mode = !int_mode &&
            (i0 == 0u || i0 == 0x3F800000u) && (i1 == 0u || i1 == 0x3F800000u) &&
            (i2 == 0u || i2 == 0x3F800000u) && (i3 == 0u || i3 == 0x3F800000u);
        if (int_mode) {
            lab[0] = i0 != 0u; lab[1] = i1 != 0u; lab[2] = i2 != 0u; lab[3] = i3 != 0u;
        } else if (flt_mode) {
            lab[0] = i0 != 0u; lab[1] = i1 != 0u; lab[2] = i2 != 0u; lab[3] = i3 != 0u;
        } else {
            #pragma unroll
            for (int b = 0; b < BATCH; b++) lab[b] = pl_raw[b] != 0;
        }

        float loss = 0.f;
        #pragma unroll
        for (int b = 0; b < BATCH; b++) {
            float lp = pol[b] / cnt[b];
            float lr = ref[b] / cnt[b];
            float mult = lab[b] ? 1.f : -1.f;
            float z = 0.1f * (lp - lr) * mult;
            float s = 1.f / (1.f + expf(-z));
            loss += 1.f - s;
        }
        out[0] = loss / (float)BATCH;
    }
}

// ---------------------------------------------------------------------------
extern "C" void kernel_launch(void* const* d_in, const int* in_sizes, int n_in,
                              void* d_out, int out_size) {
    (void)in_sizes; (void)n_in; (void)out_size;
    const float*         x  = (const float*)d_in[0];
    const float*         rx = (const float*)d_in[1];
    const int*           y  = (const int*)d_in[2];
    const unsigned char* pl = (const unsigned char*)d_in[3];
    const float*         W  = (const float*)d_in[4];
    const float*         rW = (const float*)d_in[5];
    float* out = (float*)d_out;

    k_init<<<16, 256>>>();
    k_target<<<(2 * TOKENS * 32) / 256, 256>>>(x, rx, W, rW, y);
    dim3 grid(TOKENS / BM, VOCAB / BN, 2);   // M fastest -> W tile L2 reuse
    k_gemm<<<grid, 256>>>(x, rx, W, rW);
    k_final<<<1, 256>>>(y, pl, out);
}

// round 9
// speedup vs baseline: 1.0006x; 1.0006x over previous
#include <cuda_runtime.h>
#include <cuda_bf16.h>
#include <cstdint>

#define TOKENS 2048   // B*T
#define BATCH  4
#define SEQ    512
#define HID    2048
#define VOCAB  32000

#define BM 128
#define BN 128
#define BK 32
#define LDS_PAD 40    // halves per smem row (32 + 8 pad) -> conflict-free ldmatrix

// scratch (allocation-free rule: __device__ globals)
__device__ float g_sumexp[2 * TOKENS];
__device__ float g_tgt[2 * TOKENS];

// ---------------------------------------------------------------------------
__global__ void k_init() {
    int i = blockIdx.x * blockDim.x + threadIdx.x;
    if (i < 2 * TOKENS) g_sumexp[i] = 0.f;
}

// ---------------------------------------------------------------------------
// Target logits: one warp per (model, token). Dot(x[m], W[y[m]]) over H=2048.
__global__ void k_target(const float* __restrict__ x, const float* __restrict__ rx,
                         const float* __restrict__ W, const float* __restrict__ rW,
                         const int* __restrict__ y) {
    int warp = (blockIdx.x * blockDim.x + threadIdx.x) >> 5;
    int lane = threadIdx.x & 31;
    if (warp >= 2 * TOKENS) return;
    int model = warp >> 11;            // TOKENS = 2^11
    int m     = warp & (TOKENS - 1);

    // int64-vs-int32 detection: y[0]=y[1]=-100 guaranteed by reference masking.
    // int64 layout -> int32 view [1] is the high word of -100 == -1.
    bool y64  = (y[1] == -1);
    int label = y[y64 ? 2 * m : m];

    float v = 0.f;
    if (label >= 0) {
        const float4* a4 = (const float4*)((model ? rx : x) + (size_t)m * HID);
        const float4* b4 = (const float4*)((model ? rW : W) + (size_t)label * HID);
        #pragma unroll 4
        for (int i = lane; i < HID / 4; i += 32) {
            float4 av = a4[i], bv = b4[i];
            v += av.x * bv.x + av.y * bv.y + av.z * bv.z + av.w * bv.w;
        }
    }
    #pragma unroll
    for (int s = 16; s; s >>= 1) v += __shfl_xor_sync(0xffffffffu, v, s);
    if (lane == 0) g_tgt[warp] = v;
}

// ---------------------------------------------------------------------------
__device__ __forceinline__ void ldsm_x4(uint32_t& r0, uint32_t& r1, uint32_t& r2,
                                        uint32_t& r3, uint32_t addr) {
    asm volatile("ldmatrix.sync.aligned.m8n8.x4.shared.b16 {%0,%1,%2,%3}, [%4];\n"
                 : "=r"(r0), "=r"(r1), "=r"(r2), "=r"(r3) : "r"(addr));
}
__device__ __forceinline__ void ldsm_x2(uint32_t& r0, uint32_t& r1, uint32_t addr) {
    asm volatile("ldmatrix.sync.aligned.m8n8.x2.shared.b16 {%0,%1}, [%2];\n"
                 : "=r"(r0), "=r"(r1) : "r"(addr));
}
__device__ __forceinline__ void mma16816(float* c, const uint32_t* a, const uint32_t* b) {
    asm volatile(
        "mma.sync.aligned.m16n8k16.row.col.f32.bf16.bf16.f32 "
        "{%0,%1,%2,%3}, {%4,%5,%6,%7}, {%8,%9}, {%0,%1,%2,%3};\n"
        : "+f"(c[0]), "+f"(c[1]), "+f"(c[2]), "+f"(c[3])
        : "r"(a[0]), "r"(a[1]), "r"(a[2]), "r"(a[3]), "r"(b[0]), "r"(b[1]));
}
__device__ __forceinline__ uint2 pack_bf16x4(float4 v) {
    __nv_bfloat162 lo = __floats2bfloat162_rn(v.x, v.y);
    __nv_bfloat162 hi = __floats2bfloat162_rn(v.z, v.w);
    uint2 r;
    r.x = *(uint32_t*)&lo;
    r.y = *(uint32_t*)&hi;
    return r;
}

// GEMM + online exp-sum epilogue.
// grid = (M/BM fastest, N/BN, 2 models); 256 threads = 8 warps in 2(M)x4(N),
// each warp owns a 64x32 output tile via 4x4 m16n8k16 fragments.
__global__ __launch_bounds__(256)
void k_gemm(const float* __restrict__ x, const float* __restrict__ rx,
            const float* __restrict__ W, const float* __restrict__ rW) {
    const int model = blockIdx.z;
    const float* A = model ? rx : x;
    const float* B = model ? rW : W;
    const int bm = blockIdx.x;
    const int bn = blockIdx.y;

    __shared__ __nv_bfloat16 As[2][BM * LDS_PAD];
    __shared__ __nv_bfloat16 Bs[2][BN * LDS_PAD];

    const int tid  = threadIdx.x;
    const int lane = tid & 31;
    const int w    = tid >> 5;
    const int wm   = w >> 2;   // 0..1
    const int wn   = w & 3;    // 0..3

    // Global loads: thread t covers rows (t>>3)+j*32, float4 col (t&7).
    // Per j a warp reads 4 rows x 8 lanes x 16B = 4 fully-coalesced 128B lines.
    const int glr = tid >> 3;        // 0..31
    const int glc = tid & 7;         // float4 index in the 32-float K-chunk
    const float* Ag = A + (size_t)(bm * BM + glr) * HID + glc * 4;
    const float* Bg = B + (size_t)(bn * BN + glr) * HID + glc * 4;

    float acc[4][4][4];
    #pragma unroll
    for (int i = 0; i < 4; i++)
        #pragma unroll
        for (int j = 0; j < 4; j++)
            #pragma unroll
            for (int e = 0; e < 4; e++) acc[i][j][e] = 0.f;

    uint32_t asb[2], bsb[2];
    asb[0] = (uint32_t)__cvta_generic_to_shared(&As[0][0]);
    asb[1] = (uint32_t)__cvta_generic_to_shared(&As[1][0]);
    bsb[0] = (uint32_t)__cvta_generic_to_shared(&Bs[0][0]);
    bsb[1] = (uint32_t)__cvta_generic_to_shared(&Bs[1][0]);

    float4 ra[4], rb[4];
    #pragma unroll
    for (int j = 0; j < 4; j++) {
        ra[j] = *(const float4*)(Ag + (size_t)j * 32 * HID);
        rb[j] = *(const float4*)(Bg + (size_t)j * 32 * HID);
    }
    // stage tile 0 -> buffer 0
    #pragma unroll
    for (int j = 0; j < 4; j++) {
        *(uint2*)&As[0][(glr + j * 32) * LDS_PAD + glc * 4] = pack_bf16x4(ra[j]);
        *(uint2*)&Bs[0][(glr + j * 32) * LDS_PAD + glc * 4] = pack_bf16x4(rb[j]);
    }

    const int KIT = HID / BK;   // 64
    for (int it = 0; it < KIT; ++it) {
        __syncthreads();                       // staged buffer (it&1) visible
        const int buf = it & 1;

        if (it + 1 < KIT) {
            const int ko = (it + 1) * BK;
            #pragma unroll
            for (int j = 0; j < 4; j++) {
                ra[j] = *(const float4*)(Ag + (size_t)j * 32 * HID + ko);
                rb[j] = *(const float4*)(Bg + (size_t)j * 32 * HID + ko);
            }
        }

        #pragma unroll
        for (int ks = 0; ks < 2; ks++) {
            uint32_t af[4][4];
            #pragma unroll
            for (int mi = 0; mi < 4; mi++) {
                int row = wm * 64 + mi * 16 + ((lane >> 3) & 1) * 8 + (lane & 7);
                int col = ks * 16 + (lane >> 4) * 8;
                ldsm_x4(af[mi][0], af[mi][1], af[mi][2], af[mi][3],
                        asb[buf] + (uint32_t)(row * LDS_PAD + col) * 2);
            }
            uint32_t bfrag[4][2];
            #pragma unroll
            for (int ni = 0; ni < 4; ni++) {
                int row = wn * 32 + ni * 8 + (lane & 7);
                int col = ks * 16 + ((lane >> 3) & 1) * 8;
                ldsm_x2(bfrag[ni][0], bfrag[ni][1],
                        bsb[buf] + (uint32_t)(row * LDS_PAD + col) * 2);
            }
            #pragma unroll
            for (int mi = 0; mi < 4; mi++)
                #pragma unroll
                for (int ni = 0; ni < 4; ni++)
                    mma16816(acc[mi][ni], af[mi], bfrag[ni]);
        }

        __syncthreads();                       // everyone done with buf^1 reads
        if (it + 1 < KIT) {
            const int nb = (it + 1) & 1;
            #pragma unroll
            for (int j = 0; j < 4; j++) {
                *(uint2*)&As[nb][(glr + j * 32) * LDS_PAD + glc * 4] = pack_bf16x4(ra[j]);
                *(uint2*)&Bs[nb][(glr + j * 32) * LDS_PAD + glc * 4] = pack_bf16x4(rb[j]);
            }
        }
    }

    // Epilogue: exp + row-sum over this block's 128 vocab columns.
    // c0,c1 -> row lane>>2 ; c2,c3 -> row (lane>>2)+8 ; quad lanes share a row.
    const int rowbase = bm * BM + wm * 64;
    #pragma unroll
    for (int mi = 0; mi < 4; mi++) {
        float s0 = 0.f, s1 = 0.f;
        #pragma unroll
        for (int ni = 0; ni < 4; ni++) {
            s0 += __expf(acc[mi][ni][0]) + __expf(acc[mi][ni][1]);
            s1 += __expf(acc[mi][ni][2]) + __expf(acc[mi][ni][3]);
        }
        s0 += __shfl_xor_sync(0xffffffffu, s0, 1);
        s0 += __shfl_xor_sync(0xffffffffu, s0, 2);
        s1 += __shfl_xor_sync(0xffffffffu, s1, 1);
        s1 += __shfl_xor_sync(0xffffffffu, s1, 2);
        if ((lane & 3) == 0) {
            int r = rowbase + mi * 16 + (lane >> 2);
            atomicAdd(&g_sumexp[model * TOKENS + r],     s0);
            atomicAdd(&g_sumexp[model * TOKENS + r + 8], s1);
        }
    }
}

// ---------------------------------------------------------------------------
__global__ void k_final(const int* __restrict__ y,
                        const unsigned char* __restrict__ pl_raw,
                        float* __restrict__ out) {
    __shared__ float pol[BATCH], ref[BATCH], cnt[BATCH];
    int tid = threadIdx.x;
    if (tid < BATCH) { pol[tid] = 0.f; ref[tid] = 0.f; cnt[tid] = 0.f; }
    __syncthreads();

    bool y64 = (y[1] == -1);
    for (int m = tid; m < TOKENS; m += blockDim.x) {
        int label = y[y64 ? 2 * m : m];
        if (label >= 0) {
            int b = m / SEQ;
            float p = g_tgt[m]          - logf(g_sumexp[m]);
            float r = g_tgt[TOKENS + m] - logf(g_sumexp[TOKENS + m]);
            atomicAdd(&pol[b], p);
            atomicAdd(&ref[b], r);
            atomicAdd(&cnt[b], 1.f);
        }
    }
    __syncthreads();

    if (tid == 0) {
        // preference_labels dtype hedge: int32 / float32 / byte encodings.
        const uint32_t* pi = (const uint32_t*)pl_raw;
        uint32_t i0 = pi[0], i1 = pi[1], i2 = pi[2], i3 = pi[3];
        bool lab[BATCH];
        bool int_mode = (i0 <= 1u) && (i1 <= 1u) && (i2 <= 1u) && (i3 <= 1u);
        bool flt_mode = !int_mode &&
            (i0 == 0u || i0 == 0x3F800000u) && (i1 == 0u || i1 == 0x3F800000u) &&
            (i2 == 0u || i2 == 0x3F800000u) && (i3 == 0u || i3 == 0x3F800000u);
        if (int_mode) {
            lab[0] = i0 != 0u; lab[1] = i1 != 0u; lab[2] = i2 != 0u; lab[3] = i3 != 0u;
        } else if (flt_mode) {
            lab[0] = i0 != 0u; lab[1] = i1 != 0u; lab[2] = i2 != 0u; lab[3] = i3 != 0u;
        } else {
            #pragma unroll
            for (int b = 0; b < BATCH; b++) lab[b] = pl_raw[b] != 0;
        }

        float loss = 0.f;
        #pragma unroll
        for (int b = 0; b < BATCH; b++) {
            float lp = pol[b] / cnt[b];
            float lr = ref[b] / cnt[b];
            float mult = lab[b] ? 1.f : -1.f;
            float z = 0.1f * (lp - lr) * mult;
            float s = 1.f / (1.f + expf(-z));
            loss += 1.f - s;
        }
        out[0] = loss / (float)BATCH;
    }
}

// ---------------------------------------------------------------------------
extern "C" void kernel_launch(void* const* d_in, const int* in_sizes, int n_in,
                              void* d_out, int out_size) {
    (void)in_sizes; (void)n_in; (void)out_size;
    const float*         x  = (const float*)d_in[0];
    const float*         rx = (const float*)d_in[1];
    const int*           y  = (const int*)d_in[2];
    const unsigned char* pl = (const unsigned char*)d_in[3];
    const float*         W  = (const float*)d_in[4];
    const float*         rW = (const float*)d_in[5];
    float* out = (float*)d_out;

    k_init<<<16, 256>>>();
    k_target<<<(2 * TOKENS * 32) / 256, 256>>>(x, rx, W, rW, y);
    dim3 grid(TOKENS / BM, VOCAB / BN, 2);   // M fastest -> W tile L2 reuse
    k_gemm<<<grid, 256>>>(x, rx, W, rW);
    k_final<<<1, 256>>>(y, pl, out);
}

// round 10
// speedup vs baseline: 1.0009x; 1.0003x over previous
#include <cuda_runtime.h>
#include <cuda_bf16.h>
#include <cstdint>

#define TOKENS 2048   // B*T
#define BATCH  4
#define SEQ    512
#define HID    2048
#define VOCAB  32000

#define BM 128
#define BN 128
#define BK 32
#define LDS_PAD 40    // halves per smem row (32 + 8 pad) -> conflict-free ldmatrix

// scratch (allocation-free rule: __device__ globals)
__device__ float g_sumexp[2 * TOKENS];
__device__ float g_tgt[2 * TOKENS];

// ---------------------------------------------------------------------------
__global__ void k_init() {
    int i = blockIdx.x * blockDim.x + threadIdx.x;
    if (i < 2 * TOKENS) g_sumexp[i] = 0.f;
}

// ---------------------------------------------------------------------------
// Target logits: one warp per (model, token). Dot(x[m], W[y[m]]) over H=2048.
__global__ void k_target(const float* __restrict__ x, const float* __restrict__ rx,
                         const float* __restrict__ W, const float* __restrict__ rW,
                         const int* __restrict__ y) {
    int warp = (blockIdx.x * blockDim.x + threadIdx.x) >> 5;
    int lane = threadIdx.x & 31;
    if (warp >= 2 * TOKENS) return;
    int model = warp >> 11;            // TOKENS = 2^11
    int m     = warp & (TOKENS - 1);

    // int64-vs-int32 detection: y[0]=y[1]=-100 guaranteed by reference masking.
    // int64 layout -> int32 view [1] is the high word of -100 == -1.
    bool y64  = (y[1] == -1);
    int label = y[y64 ? 2 * m : m];

    float v = 0.f;
    if (label >= 0) {
        const float4* a4 = (const float4*)((model ? rx : x) + (size_t)m * HID);
        const float4* b4 = (const float4*)((model ? rW : W) + (size_t)label * HID);
        #pragma unroll 4
        for (int i = lane; i < HID / 4; i += 32) {
            float4 av = a4[i], bv = b4[i];
            v += av.x * bv.x + av.y * bv.y + av.z * bv.z + av.w * bv.w;
        }
    }
    #pragma unroll
    for (int s = 16; s; s >>= 1) v += __shfl_xor_sync(0xffffffffu, v, s);
    if (lane == 0) g_tgt[warp] = v;
}

// ---------------------------------------------------------------------------
__device__ __forceinline__ void ldsm_x4(uint32_t& r0, uint32_t& r1, uint32_t& r2,
                                        uint32_t& r3, uint32_t addr) {
    asm volatile("ldmatrix.sync.aligned.m8n8.x4.shared.b16 {%0,%1,%2,%3}, [%4];\n"
                 : "=r"(r0), "=r"(r1), "=r"(r2), "=r"(r3) : "r"(addr));
}
__device__ __forceinline__ void ldsm_x2(uint32_t& r0, uint32_t& r1, uint32_t addr) {
    asm volatile("ldmatrix.sync.aligned.m8n8.x2.shared.b16 {%0,%1}, [%2];\n"
                 : "=r"(r0), "=r"(r1) : "r"(addr));
}
__device__ __forceinline__ void mma16816(float* c, const uint32_t* a, const uint32_t* b) {
    asm volatile(
        "mma.sync.aligned.m16n8k16.row.col.f32.bf16.bf16.f32 "
        "{%0,%1,%2,%3}, {%4,%5,%6,%7}, {%8,%9}, {%0,%1,%2,%3};\n"
        : "+f"(c[0]), "+f"(c[1]), "+f"(c[2]), "+f"(c[3])
        : "r"(a[0]), "r"(a[1]), "r"(a[2]), "r"(a[3]), "r"(b[0]), "r"(b[1]));
}
__device__ __forceinline__ uint2 pack_bf16x4(float4 v) {
    __nv_bfloat162 lo = __floats2bfloat162_rn(v.x, v.y);
    __nv_bfloat162 hi = __floats2bfloat162_rn(v.z, v.w);
    uint2 r;
    r.x = *(uint32_t*)&lo;
    r.y = *(uint32_t*)&hi;
    return r;
}

// GEMM + online exp-sum epilogue.
// grid = (M/BM fastest, N/BN, 2 models); 256 threads = 8 warps in 2(M)x4(N),
// each warp owns a 64x32 output tile via 4x4 m16n8k16 fragments.
__global__ __launch_bounds__(256)
void k_gemm(const float* __restrict__ x, const float* __restrict__ rx,
            const float* __restrict__ W, const float* __restrict__ rW) {
    const int model = blockIdx.z;
    const float* A = model ? rx : x;
    const float* B = model ? rW : W;
    const int bm = blockIdx.x;
    const int bn = blockIdx.y;

    __shared__ __nv_bfloat16 As[2][BM * LDS_PAD];
    __shared__ __nv_bfloat16 Bs[2][BN * LDS_PAD];

    const int tid  = threadIdx.x;
    const int lane = tid & 31;
    const int w    = tid >> 5;
    const int wm   = w >> 2;   // 0..1
    const int wn   = w & 3;    // 0..3

    // Global loads: thread t covers rows (t>>3)+j*32, float4 col (t&7).
    // Per j a warp reads 4 rows x 8 lanes x 16B = 4 fully-coalesced 128B lines.
    const int glr = tid >> 3;        // 0..31
    const int glc = tid & 7;         // float4 index in the 32-float K-chunk
    const float* Ag = A + (size_t)(bm * BM + glr) * HID + glc * 4;
    const float* Bg = B + (size_t)(bn * BN + glr) * HID + glc * 4;

    float acc[4][4][4];
    #pragma unroll
    for (int i = 0; i < 4; i++)
        #pragma unroll
        for (int j = 0; j < 4; j++)
            #pragma unroll
            for (int e = 0; e < 4; e++) acc[i][j][e] = 0.f;

    uint32_t asb[2], bsb[2];
    asb[0] = (uint32_t)__cvta_generic_to_shared(&As[0][0]);
    asb[1] = (uint32_t)__cvta_generic_to_shared(&As[1][0]);
    bsb[0] = (uint32_t)__cvta_generic_to_shared(&Bs[0][0]);
    bsb[1] = (uint32_t)__cvta_generic_to_shared(&Bs[1][0]);

    float4 ra[4], rb[4];
    #pragma unroll
    for (int j = 0; j < 4; j++) {
        ra[j] = *(const float4*)(Ag + (size_t)j * 32 * HID);
        rb[j] = *(const float4*)(Bg + (size_t)j * 32 * HID);
    }
    // stage tile 0 -> buffer 0
    #pragma unroll
    for (int j = 0; j < 4; j++) {
        *(uint2*)&As[0][(glr + j * 32) * LDS_PAD + glc * 4] = pack_bf16x4(ra[j]);
        *(uint2*)&Bs[0][(glr + j * 32) * LDS_PAD + glc * 4] = pack_bf16x4(rb[j]);
    }

    const int KIT = HID / BK;   // 64
    for (int it = 0; it < KIT; ++it) {
        __syncthreads();                       // staged buffer (it&1) visible
        const int buf = it & 1;

        if (it + 1 < KIT) {
            const int ko = (it + 1) * BK;
            #pragma unroll
            for (int j = 0; j < 4; j++) {
                ra[j] = *(const float4*)(Ag + (size_t)j * 32 * HID + ko);
                rb[j] = *(const float4*)(Bg + (size_t)j * 32 * HID + ko);
            }
        }

        #pragma unroll
        for (int ks = 0; ks < 2; ks++) {
            uint32_t af[4][4];
            #pragma unroll
            for (int mi = 0; mi < 4; mi++) {
                int row = wm * 64 + mi * 16 + ((lane >> 3) & 1) * 8 + (lane & 7);
                int col = ks * 16 + (lane >> 4) * 8;
                ldsm_x4(af[mi][0], af[mi][1], af[mi][2], af[mi][3],
                        asb[buf] + (uint32_t)(row * LDS_PAD + col) * 2);
            }
            uint32_t bfrag[4][2];
            #pragma unroll
            for (int ni = 0; ni < 4; ni++) {
                int row = wn * 32 + ni * 8 + (lane & 7);
                int col = ks * 16 + ((lane >> 3) & 1) * 8;
                ldsm_x2(bfrag[ni][0], bfrag[ni][1],
                        bsb[buf] + (uint32_t)(row * LDS_PAD + col) * 2);
            }
            #pragma unroll
            for (int mi = 0; mi < 4; mi++)
                #pragma unroll
                for (int ni = 0; ni < 4; ni++)
                    mma16816(acc[mi][ni], af[mi], bfrag[ni]);
        }

        __syncthreads();                       // everyone done with buf^1 reads
        if (it + 1 < KIT) {
            const int nb = (it + 1) & 1;
            #pragma unroll
            for (int j = 0; j < 4; j++) {
                *(uint2*)&As[nb][(glr + j * 32) * LDS_PAD + glc * 4] = pack_bf16x4(ra[j]);
                *(uint2*)&Bs[nb][(glr + j * 32) * LDS_PAD + glc * 4] = pack_bf16x4(rb[j]);
            }
        }
    }

    // Epilogue: exp + row-sum over this block's 128 vocab columns.
    // c0,c1 -> row lane>>2 ; c2,c3 -> row (lane>>2)+8 ; quad lanes share a row.
    const int rowbase = bm * BM + wm * 64;
    #pragma unroll
    for (int mi = 0; mi < 4; mi++) {
        float s0 = 0.f, s1 = 0.f;
        #pragma unroll
        for (int ni = 0; ni < 4; ni++) {
            s0 += __expf(acc[mi][ni][0]) + __expf(acc[mi][ni][1]);
            s1 += __expf(acc[mi][ni][2]) + __expf(acc[mi][ni][3]);
        }
        s0 += __shfl_xor_sync(0xffffffffu, s0, 1);
        s0 += __shfl_xor_sync(0xffffffffu, s0, 2);
        s1 += __shfl_xor_sync(0xffffffffu, s1, 1);
        s1 += __shfl_xor_sync(0xffffffffu, s1, 2);
        if ((lane & 3) == 0) {
            int r = rowbase + mi * 16 + (lane >> 2);
            atomicAdd(&g_sumexp[model * TOKENS + r],     s0);
            atomicAdd(&g_sumexp[model * TOKENS + r + 8], s1);
        }
    }
}

// ---------------------------------------------------------------------------
__global__ void k_final(const int* __restrict__ y,
                        const unsigned char* __restrict__ pl_raw,
                        float* __restrict__ out) {
    __shared__ float pol[BATCH], ref[BATCH], cnt[BATCH];
    int tid = threadIdx.x;
    if (tid < BATCH) { pol[tid] = 0.f; ref[tid] = 0.f; cnt[tid] = 0.f; }
    __syncthreads();

    bool y64 = (y[1] == -1);
    for (int m = tid; m < TOKENS; m += blockDim.x) {
        int label = y[y64 ? 2 * m : m];
        if (label >= 0) {
            int b = m / SEQ;
            float p = g_tgt[m]          - logf(g_sumexp[m]);
            float r = g_tgt[TOKENS + m] - logf(g_sumexp[TOKENS + m]);
            atomicAdd(&pol[b], p);
            atomicAdd(&ref[b], r);
            atomicAdd(&cnt[b], 1.f);
        }
    }
    __syncthreads();

    if (tid == 0) {
        // preference_labels dtype hedge: int32 / float32 / byte encodings.
        const uint32_t* pi = (const uint32_t*)pl_raw;
        uint32_t i0 = pi[0], i1 = pi[1], i2 = pi[2], i3 = pi[3];
        bool lab[BATCH];
        bool int_mode = (i0 <= 1u) && (i1 <= 1u) && (i2 <= 1u) && (i3 <= 1u);
        bool flt_mode = !int_mode &&
            (i0 == 0u || i0 == 0x3F800000u) && (i1 == 0u || i1 == 0x3F800000u) &&
            (i2 == 0u || i2 == 0x3F800000u) && (i3 == 0u || i3 == 0x3F800000u);
        if (int_mode) {
            lab[0] = i0 != 0u; lab[1] = i1 != 0u; lab[2] = i2 != 0u; lab[3] = i3 != 0u;
        } else if (flt_mode) {
            lab[0] = i0 != 0u; lab[1] = i1 != 0u; lab[2] = i2 != 0u; lab[3] = i3 != 0u;
        } else {
            #pragma unroll
            for (int b = 0; b < BATCH; b++) lab[b] = pl_raw[b] != 0;
        }

        float loss = 0.f;
        #pragma unroll
        for (int b = 0; b < BATCH; b++) {
            float lp = pol[b] / cnt[b];
            float lr = ref[b] / cnt[b];
            float mult = lab[b] ? 1.f : -1.f;
            float z = 0.1f * (lp - lr) * mult;
            float s = 1.f / (1.f + expf(-z));
            loss += 1.f - s;
        }
        out[0] = loss / (float)BATCH;
    }
}

// ---------------------------------------------------------------------------
extern "C" void kernel_launch(void* const* d_in, const int* in_sizes, int n_in,
                              void* d_out, int out_size) {
    (void)in_sizes; (void)n_in; (void)out_size;
    const float*         x  = (const float*)d_in[0];
    const float*         rx = (const float*)d_in[1];
    const int*           y  = (const int*)d_in[2];
    const unsigned char* pl = (const unsigned char*)d_in[3];
    const float*         W  = (const float*)d_in[4];
    const float*         rW = (const float*)d_in[5];
    float* out = (float*)d_out;

    k_init<<<16, 256>>>();
    k_target<<<(2 * TOKENS * 32) / 256, 256>>>(x, rx, W, rW, y);
    dim3 grid(TOKENS / BM, VOCAB / BN, 2);   // M fastest -> W tile L2 reuse
    k_gemm<<<grid, 256>>>(x, rx, W, rW);
    k_final<<<1, 256>>>(y, pl, out);
}

// round 11
// speedup vs baseline: 1.0017x; 1.0008x over previous
#include <cuda_runtime.h>
#include <cuda_bf16.h>
#include <cstdint>

#define TOKENS 2048   // B*T
#define BATCH  4
#define SEQ    512
#define HID    2048
#define VOCAB  32000

#define BM 128
#define BN 128
#define BK 32
#define LDS_PAD 40    // halves per smem row (32 + 8 pad) -> conflict-free ldmatrix

// scratch (allocation-free rule: __device__ globals)
__device__ float g_sumexp[2 * TOKENS];
__device__ float g_tgt[2 * TOKENS];

// ---------------------------------------------------------------------------
__global__ void k_init() {
    int i = blockIdx.x * blockDim.x + threadIdx.x;
    if (i < 2 * TOKENS) g_sumexp[i] = 0.f;
}

// ---------------------------------------------------------------------------
// Target logits: one warp per (model, token). Dot(x[m], W[y[m]]) over H=2048.
__global__ void k_target(const float* __restrict__ x, const float* __restrict__ rx,
                         const float* __restrict__ W, const float* __restrict__ rW,
                         const int* __restrict__ y) {
    int warp = (blockIdx.x * blockDim.x + threadIdx.x) >> 5;
    int lane = threadIdx.x & 31;
    if (warp >= 2 * TOKENS) return;
    int model = warp >> 11;            // TOKENS = 2^11
    int m     = warp & (TOKENS - 1);

    // int64-vs-int32 detection: y[0]=y[1]=-100 guaranteed by reference masking.
    // int64 layout -> int32 view [1] is the high word of -100 == -1.
    bool y64  = (y[1] == -1);
    int label = y[y64 ? 2 * m : m];

    float v = 0.f;
    if (label >= 0) {
        const float4* a4 = (const float4*)((model ? rx : x) + (size_t)m * HID);
        const float4* b4 = (const float4*)((model ? rW : W) + (size_t)label * HID);
        #pragma unroll 4
        for (int i = lane; i < HID / 4; i += 32) {
            float4 av = a4[i], bv = b4[i];
            v += av.x * bv.x + av.y * bv.y + av.z * bv.z + av.w * bv.w;
        }
    }
    #pragma unroll
    for (int s = 16; s; s >>= 1) v += __shfl_xor_sync(0xffffffffu, v, s);
    if (lane == 0) g_tgt[warp] = v;
}

// ---------------------------------------------------------------------------
__device__ __forceinline__ void ldsm_x4(uint32_t& r0, uint32_t& r1, uint32_t& r2,
                                        uint32_t& r3, uint32_t addr) {
    asm volatile("ldmatrix.sync.aligned.m8n8.x4.shared.b16 {%0,%1,%2,%3}, [%4];\n"
                 : "=r"(r0), "=r"(r1), "=r"(r2), "=r"(r3) : "r"(addr));
}
__device__ __forceinline__ void ldsm_x2(uint32_t& r0, uint32_t& r1, uint32_t addr) {
    asm volatile("ldmatrix.sync.aligned.m8n8.x2.shared.b16 {%0,%1}, [%2];\n"
                 : "=r"(r0), "=r"(r1) : "r"(addr));
}
__device__ __forceinline__ void mma16816(float* c, const uint32_t* a, const uint32_t* b) {
    asm volatile(
        "mma.sync.aligned.m16n8k16.row.col.f32.bf16.bf16.f32 "
        "{%0,%1,%2,%3}, {%4,%5,%6,%7}, {%8,%9}, {%0,%1,%2,%3};\n"
        : "+f"(c[0]), "+f"(c[1]), "+f"(c[2]), "+f"(c[3])
        : "r"(a[0]), "r"(a[1]), "r"(a[2]), "r"(a[3]), "r"(b[0]), "r"(b[1]));
}
__device__ __forceinline__ uint2 pack_bf16x4(float4 v) {
    __nv_bfloat162 lo = __floats2bfloat162_rn(v.x, v.y);
    __nv_bfloat162 hi = __floats2bfloat162_rn(v.z, v.w);
    uint2 r;
    r.x = *(uint32_t*)&lo;
    r.y = *(uint32_t*)&hi;
    return r;
}

// GEMM + online exp-sum epilogue.
// grid = (M/BM fastest, N/BN, 2 models); 256 threads = 8 warps in 2(M)x4(N),
// each warp owns a 64x32 output tile via 4x4 m16n8k16 fragments.
__global__ __launch_bounds__(256)
void k_gemm(const float* __restrict__ x, const float* __restrict__ rx,
            const float* __restrict__ W, const float* __restrict__ rW) {
    const int model = blockIdx.z;
    const float* A = model ? rx : x;
    const float* B = model ? rW : W;
    const int bm = blockIdx.x;
    const int bn = blockIdx.y;

    __shared__ __nv_bfloat16 As[2][BM * LDS_PAD];
    __shared__ __nv_bfloat16 Bs[2][BN * LDS_PAD];

    const int tid  = threadIdx.x;
    const int lane = tid & 31;
    const int w    = tid >> 5;
    const int wm   = w >> 2;   // 0..1
    const int wn   = w & 3;    // 0..3

    // Global loads: thread t covers rows (t>>3)+j*32, float4 col (t&7).
    // Per j a warp reads 4 rows x 8 lanes x 16B = 4 fully-coalesced 128B lines.
    const int glr = tid >> 3;        // 0..31
    const int glc = tid & 7;         // float4 index in the 32-float K-chunk
    const float* Ag = A + (size_t)(bm * BM + glr) * HID + glc * 4;
    const float* Bg = B + (size_t)(bn * BN + glr) * HID + glc * 4;

    float acc[4][4][4];
    #pragma unroll
    for (int i = 0; i < 4; i++)
        #pragma unroll
        for (int j = 0; j < 4; j++)
            #pragma unroll
            for (int e = 0; e < 4; e++) acc[i][j][e] = 0.f;

    uint32_t asb[2], bsb[2];
    asb[0] = (uint32_t)__cvta_generic_to_shared(&As[0][0]);
    asb[1] = (uint32_t)__cvta_generic_to_shared(&As[1][0]);
    bsb[0] = (uint32_t)__cvta_generic_to_shared(&Bs[0][0]);
    bsb[1] = (uint32_t)__cvta_generic_to_shared(&Bs[1][0]);

    float4 ra[4], rb[4];
    #pragma unroll
    for (int j = 0; j < 4; j++) {
        ra[j] = *(const float4*)(Ag + (size_t)j * 32 * HID);
        rb[j] = *(const float4*)(Bg + (size_t)j * 32 * HID);
    }
    // stage tile 0 -> buffer 0
    #pragma unroll
    for (int j = 0; j < 4; j++) {
        *(uint2*)&As[0][(glr + j * 32) * LDS_PAD + glc * 4] = pack_bf16x4(ra[j]);
        *(uint2*)&Bs[0][(glr + j * 32) * LDS_PAD + glc * 4] = pack_bf16x4(rb[j]);
    }

    const int KIT = HID / BK;   // 64
    for (int it = 0; it < KIT; ++it) {
        __syncthreads();                       // staged buffer (it&1) visible
        const int buf = it & 1;

        if (it + 1 < KIT) {
            const int ko = (it + 1) * BK;
            #pragma unroll
            for (int j = 0; j < 4; j++) {
                ra[j] = *(const float4*)(Ag + (size_t)j * 32 * HID + ko);
                rb[j] = *(const float4*)(Bg + (size_t)j * 32 * HID + ko);
            }
        }

        #pragma unroll
        for (int ks = 0; ks < 2; ks++) {
            uint32_t af[4][4];
            #pragma unroll
            for (int mi = 0; mi < 4; mi++) {
                int row = wm * 64 + mi * 16 + ((lane >> 3) & 1) * 8 + (lane & 7);
                int col = ks * 16 + (lane >> 4) * 8;
                ldsm_x4(af[mi][0], af[mi][1], af[mi][2], af[mi][3],
                        asb[buf] + (uint32_t)(row * LDS_PAD + col) * 2);
            }
            uint32_t bfrag[4][2];
            #pragma unroll
            for (int ni = 0; ni < 4; ni++) {
                int row = wn * 32 + ni * 8 + (lane & 7);
                int col = ks * 16 + ((lane >> 3) & 1) * 8;
                ldsm_x2(bfrag[ni][0], bfrag[ni][1],
                        bsb[buf] + (uint32_t)(row * LDS_PAD + col) * 2);
            }
            #pragma unroll
            for (int mi = 0; mi < 4; mi++)
                #pragma unroll
                for (int ni = 0; ni < 4; ni++)
                    mma16816(acc[mi][ni], af[mi], bfrag[ni]);
        }

        __syncthreads();                       // everyone done with buf^1 reads
        if (it + 1 < KIT) {
            const int nb = (it + 1) & 1;
            #pragma unroll
            for (int j = 0; j < 4; j++) {
                *(uint2*)&As[nb][(glr + j * 32) * LDS_PAD + glc * 4] = pack_bf16x4(ra[j]);
                *(uint2*)&Bs[nb][(glr + j * 32) * LDS_PAD + glc * 4] = pack_bf16x4(rb[j]);
            }
        }
    }

    // Epilogue: exp + row-sum over this block's 128 vocab columns.
    // c0,c1 -> row lane>>2 ; c2,c3 -> row (lane>>2)+8 ; quad lanes share a row.
    const int rowbase = bm * BM + wm * 64;
    #pragma unroll
    for (int mi = 0; mi < 4; mi++) {
        float s0 = 0.f, s1 = 0.f;
        #pragma unroll
        for (int ni = 0; ni < 4; ni++) {
            s0 += __expf(acc[mi][ni][0]) + __expf(acc[mi][ni][1]);
            s1 += __expf(acc[mi][ni][2]) + __expf(acc[mi][ni][3]);
        }
        s0 += __shfl_xor_sync(0xffffffffu, s0, 1);
        s0 += __shfl_xor_sync(0xffffffffu, s0, 2);
        s1 += __shfl_xor_sync(0xffffffffu, s1, 1);
        s1 += __shfl_xor_sync(0xffffffffu, s1, 2);
        if ((lane & 3) == 0) {
            int r = rowbase + mi * 16 + (lane >> 2);
            atomicAdd(&g_sumexp[model * TOKENS + r],     s0);
            atomicAdd(&g_sumexp[model * TOKENS + r + 8], s1);
        }
    }
}

// ---------------------------------------------------------------------------
__global__ void k_final(const int* __restrict__ y,
                        const unsigned char* __restrict__ pl_raw,
                        float* __restrict__ out) {
    __shared__ float pol[BATCH], ref[BATCH], cnt[BATCH];
    int tid = threadIdx.x;
    if (tid < BATCH) { pol[tid] = 0.f; ref[tid] = 0.f; cnt[tid] = 0.f; }
    __syncthreads();

    bool y64 = (y[1] == -1);
    for (int m = tid; m < TOKENS; m += blockDim.x) {
        int label = y[y64 ? 2 * m : m];
        if (label >= 0) {
            int b = m / SEQ;
            float p = g_tgt[m]          - logf(g_sumexp[m]);
            float r = g_tgt[TOKENS + m] - logf(g_sumexp[TOKENS + m]);
            atomicAdd(&pol[b], p);
            atomicAdd(&ref[b], r);
            atomicAdd(&cnt[b], 1.f);
        }
    }
    __syncthreads();

    if (tid == 0) {
        // preference_labels dtype hedge: int32 / float32 / byte encodings.
        const uint32_t* pi = (const uint32_t*)pl_raw;
        uint32_t i0 = pi[0], i1 = pi[1], i2 = pi[2], i3 = pi[3];
        bool lab[BATCH];
        bool int_mode = (i0 <= 1u) && (i1 <= 1u) && (i2 <= 1u) && (i3 <= 1u);
        bool flt_mode = !int_mode &&
            (i0 == 0u || i0 == 0x3F800000u) && (i1 == 0u || i1 == 0x3F800000u) &&
            (i2 == 0u || i2 == 0x3F800000u) && (i3 == 0u || i3 == 0x3F800000u);
        if (int_mode) {
            lab[0] = i0 != 0u; lab[1] = i1 != 0u; lab[2] = i2 != 0u; lab[3] = i3 != 0u;
        } else if (flt_mode) {
            lab[0] = i0 != 0u; lab[1] = i1 != 0u; lab[2] = i2 != 0u; lab[3] = i3 != 0u;
        } else {
            #pragma unroll
            for (int b = 0; b < BATCH; b++) lab[b] = pl_raw[b] != 0;
        }

        float loss = 0.f;
        #pragma unroll
        for (int b = 0; b < BATCH; b++) {
            float lp = pol[b] / cnt[b];
            float lr = ref[b] / cnt[b];
            float mult = lab[b] ? 1.f : -1.f;
            float z = 0.1f * (lp - lr) * mult;
            float s = 1.f / (1.f + expf(-z));
            loss += 1.f - s;
        }
        out[0] = loss / (float)BATCH;
    }
}

// ---------------------------------------------------------------------------
extern "C" void kernel_launch(void* const* d_in, const int* in_sizes, int n_in,
                              void* d_out, int out_size) {
    (void)in_sizes; (void)n_in; (void)out_size;
    const float*         x  = (const float*)d_in[0];
    const float*         rx = (const float*)d_in[1];
    const int*           y  = (const int*)d_in[2];
    const unsigned char* pl = (const unsigned char*)d_in[3];
    const float*         W  = (const float*)d_in[4];
    const float*         rW = (const float*)d_in[5];
    float* out = (float*)d_out;

    k_init<<<16, 256>>>();
    k_target<<<(2 * TOKENS * 32) / 256, 256>>>(x, rx, W, rW, y);
    dim3 grid(TOKENS / BM, VOCAB / BN, 2);   // M fastest -> W tile L2 reuse
    k_gemm<<<grid, 256>>>(x, rx, W, rW);
    k_final<<<1, 256>>>(y, pl, out);
}

// round 12
// speedup vs baseline: 1.0018x; 1.0001x over previous
#include <cuda_runtime.h>
#include <cuda_bf16.h>
#include <cstdint>

#define TOKENS 2048   // B*T
#define BATCH  4
#define SEQ    512
#define HID    2048
#define VOCAB  32000

#define BM 128
#define BN 128
#define BK 32
#define LDS_PAD 40    // halves per smem row (32 + 8 pad) -> conflict-free ldmatrix

// scratch (allocation-free rule: __device__ globals)
__device__ float g_sumexp[2 * TOKENS];
__device__ float g_tgt[2 * TOKENS];

// ---------------------------------------------------------------------------
__global__ void k_init() {
    int i = blockIdx.x * blockDim.x + threadIdx.x;
    if (i < 2 * TOKENS) g_sumexp[i] = 0.f;
}

// ---------------------------------------------------------------------------
// Target logits: one warp per (model, token). Dot(x[m], W[y[m]]) over H=2048.
__global__ void k_target(const float* __restrict__ x, const float* __restrict__ rx,
                         const float* __restrict__ W, const float* __restrict__ rW,
                         const int* __restrict__ y) {
    int warp = (blockIdx.x * blockDim.x + threadIdx.x) >> 5;
    int lane = threadIdx.x & 31;
    if (warp >= 2 * TOKENS) return;
    int model = warp >> 11;            // TOKENS = 2^11
    int m     = warp & (TOKENS - 1);

    // int64-vs-int32 detection: y[0]=y[1]=-100 guaranteed by reference masking.
    // int64 layout -> int32 view [1] is the high word of -100 == -1.
    bool y64  = (y[1] == -1);
    int label = y[y64 ? 2 * m : m];

    float v = 0.f;
    if (label >= 0) {
        const float4* a4 = (const float4*)((model ? rx : x) + (size_t)m * HID);
        const float4* b4 = (const float4*)((model ? rW : W) + (size_t)label * HID);
        #pragma unroll 4
        for (int i = lane; i < HID / 4; i += 32) {
            float4 av = a4[i], bv = b4[i];
            v += av.x * bv.x + av.y * bv.y + av.z * bv.z + av.w * bv.w;
        }
    }
    #pragma unroll
    for (int s = 16; s; s >>= 1) v += __shfl_xor_sync(0xffffffffu, v, s);
    if (lane == 0) g_tgt[warp] = v;
}

// ---------------------------------------------------------------------------
__device__ __forceinline__ void ldsm_x4(uint32_t& r0, uint32_t& r1, uint32_t& r2,
                                        uint32_t& r3, uint32_t addr) {
    asm volatile("ldmatrix.sync.aligned.m8n8.x4.shared.b16 {%0,%1,%2,%3}, [%4];\n"
                 : "=r"(r0), "=r"(r1), "=r"(r2), "=r"(r3) : "r"(addr));
}
__device__ __forceinline__ void ldsm_x2(uint32_t& r0, uint32_t& r1, uint32_t addr) {
    asm volatile("ldmatrix.sync.aligned.m8n8.x2.shared.b16 {%0,%1}, [%2];\n"
                 : "=r"(r0), "=r"(r1) : "r"(addr));
}
__device__ __forceinline__ void mma16816(float* c, const uint32_t* a, const uint32_t* b) {
    asm volatile(
        "mma.sync.aligned.m16n8k16.row.col.f32.bf16.bf16.f32 "
        "{%0,%1,%2,%3}, {%4,%5,%6,%7}, {%8,%9}, {%0,%1,%2,%3};\n"
        : "+f"(c[0]), "+f"(c[1]), "+f"(c[2]), "+f"(c[3])
        : "r"(a[0]), "r"(a[1]), "r"(a[2]), "r"(a[3]), "r"(b[0]), "r"(b[1]));
}
__device__ __forceinline__ uint2 pack_bf16x4(float4 v) {
    __nv_bfloat162 lo = __floats2bfloat162_rn(v.x, v.y);
    __nv_bfloat162 hi = __floats2bfloat162_rn(v.z, v.w);
    uint2 r;
    r.x = *(uint32_t*)&lo;
    r.y = *(uint32_t*)&hi;
    return r;
}

// GEMM + online exp-sum epilogue.
// grid = (M/BM fastest, N/BN, 2 models); 256 threads = 8 warps in 2(M)x4(N),
// each warp owns a 64x32 output tile via 4x4 m16n8k16 fragments.
__global__ __launch_bounds__(256)
void k_gemm(const float* __restrict__ x, const float* __restrict__ rx,
            const float* __restrict__ W, const float* __restrict__ rW) {
    const int model = blockIdx.z;
    const float* A = model ? rx : x;
    const float* B = model ? rW : W;
    const int bm = blockIdx.x;
    const int bn = blockIdx.y;

    __shared__ __nv_bfloat16 As[2][BM * LDS_PAD];
    __shared__ __nv_bfloat16 Bs[2][BN * LDS_PAD];

    const int tid  = threadIdx.x;
    const int lane = tid & 31;
    const int w    = tid >> 5;
    const int wm   = w >> 2;   // 0..1
    const int wn   = w & 3;    // 0..3

    // Global loads: thread t covers rows (t>>3)+j*32, float4 col (t&7).
    // Per j a warp reads 4 rows x 8 lanes x 16B = 4 fully-coalesced 128B lines.
    const int glr = tid >> 3;        // 0..31
    const int glc = tid & 7;         // float4 index in the 32-float K-chunk
    const float* Ag = A + (size_t)(bm * BM + glr) * HID + glc * 4;
    const float* Bg = B + (size_t)(bn * BN + glr) * HID + glc * 4;

    float acc[4][4][4];
    #pragma unroll
    for (int i = 0; i < 4; i++)
        #pragma unroll
        for (int j = 0; j < 4; j++)
            #pragma unroll
            for (int e = 0; e < 4; e++) acc[i][j][e] = 0.f;

    uint32_t asb[2], bsb[2];
    asb[0] = (uint32_t)__cvta_generic_to_shared(&As[0][0]);
    asb[1] = (uint32_t)__cvta_generic_to_shared(&As[1][0]);
    bsb[0] = (uint32_t)__cvta_generic_to_shared(&Bs[0][0]);
    bsb[1] = (uint32_t)__cvta_generic_to_shared(&Bs[1][0]);

    float4 ra[4], rb[4];
    #pragma unroll
    for (int j = 0; j < 4; j++) {
        ra[j] = *(const float4*)(Ag + (size_t)j * 32 * HID);
        rb[j] = *(const float4*)(Bg + (size_t)j * 32 * HID);
    }
    // stage tile 0 -> buffer 0
    #pragma unroll
    for (int j = 0; j < 4; j++) {
        *(uint2*)&As[0][(glr + j * 32) * LDS_PAD + glc * 4] = pack_bf16x4(ra[j]);
        *(uint2*)&Bs[0][(glr + j * 32) * LDS_PAD + glc * 4] = pack_bf16x4(rb[j]);
    }

    const int KIT = HID / BK;   // 64
    for (int it = 0; it < KIT; ++it) {
        __syncthreads();                       // staged buffer (it&1) visible
        const int buf = it & 1;

        if (it + 1 < KIT) {
            const int ko = (it + 1) * BK;
            #pragma unroll
            for (int j = 0; j < 4; j++) {
                ra[j] = *(const float4*)(Ag + (size_t)j * 32 * HID + ko);
                rb[j] = *(const float4*)(Bg + (size_t)j * 32 * HID + ko);
            }
        }

        #pragma unroll
        for (int ks = 0; ks < 2; ks++) {
            uint32_t af[4][4];
            #pragma unroll
            for (int mi = 0; mi < 4; mi++) {
                int row = wm * 64 + mi * 16 + ((lane >> 3) & 1) * 8 + (lane & 7);
                int col = ks * 16 + (lane >> 4) * 8;
                ldsm_x4(af[mi][0], af[mi][1], af[mi][2], af[mi][3],
                        asb[buf] + (uint32_t)(row * LDS_PAD + col) * 2);
            }
            uint32_t bfrag[4][2];
            #pragma unroll
            for (int ni = 0; ni < 4; ni++) {
                int row = wn * 32 + ni * 8 + (lane & 7);
                int col = ks * 16 + ((lane >> 3) & 1) * 8;
                ldsm_x2(bfrag[ni][0], bfrag[ni][1],
                        bsb[buf] + (uint32_t)(row * LDS_PAD + col) * 2);
            }
            #pragma unroll
            for (int mi = 0; mi < 4; mi++)
                #pragma unroll
                for (int ni = 0; ni < 4; ni++)
                    mma16816(acc[mi][ni], af[mi], bfrag[ni]);
        }

        __syncthreads();                       // everyone done with buf^1 reads
        if (it + 1 < KIT) {
            const int nb = (it + 1) & 1;
            #pragma unroll
            for (int j = 0; j < 4; j++) {
                *(uint2*)&As[nb][(glr + j * 32) * LDS_PAD + glc * 4] = pack_bf16x4(ra[j]);
                *(uint2*)&Bs[nb][(glr + j * 32) * LDS_PAD + glc * 4] = pack_bf16x4(rb[j]);
            }
        }
    }

    // Epilogue: exp + row-sum over this block's 128 vocab columns.
    // c0,c1 -> row lane>>2 ; c2,c3 -> row (lane>>2)+8 ; quad lanes share a row.
    const int rowbase = bm * BM + wm * 64;
    #pragma unroll
    for (int mi = 0; mi < 4; mi++) {
        float s0 = 0.f, s1 = 0.f;
        #pragma unroll
        for (int ni = 0; ni < 4; ni++) {
            s0 += __expf(acc[mi][ni][0]) + __expf(acc[mi][ni][1]);
            s1 += __expf(acc[mi][ni][2]) + __expf(acc[mi][ni][3]);
        }
        s0 += __shfl_xor_sync(0xffffffffu, s0, 1);
        s0 += __shfl_xor_sync(0xffffffffu, s0, 2);
        s1 += __shfl_xor_sync(0xffffffffu, s1, 1);
        s1 += __shfl_xor_sync(0xffffffffu, s1, 2);
        if ((lane & 3) == 0) {
            int r = rowbase + mi * 16 + (lane >> 2);
            atomicAdd(&g_sumexp[model * TOKENS + r],     s0);
            atomicAdd(&g_sumexp[model * TOKENS + r + 8], s1);
        }
    }
}

// ---------------------------------------------------------------------------
__global__ void k_final(const int* __restrict__ y,
                        const unsigned char* __restrict__ pl_raw,
                        float* __restrict__ out) {
    __shared__ float pol[BATCH], ref[BATCH], cnt[BATCH];
    int tid = threadIdx.x;
    if (tid < BATCH) { pol[tid] = 0.f; ref[tid] = 0.f; cnt[tid] = 0.f; }
    __syncthreads();

    bool y64 = (y[1] == -1);
    for (int m = tid; m < TOKENS; m += blockDim.x) {
        int label = y[y64 ? 2 * m : m];
        if (label >= 0) {
            int b = m / SEQ;
            float p = g_tgt[m]          - logf(g_sumexp[m]);
            float r = g_tgt[TOKENS + m] - logf(g_sumexp[TOKENS + m]);
            atomicAdd(&pol[b], p);
            atomicAdd(&ref[b], r);
            atomicAdd(&cnt[b], 1.f);
        }
    }
    __syncthreads();

    if (tid == 0) {
        // preference_labels dtype hedge: int32 / float32 / byte encodings.
        const uint32_t* pi = (const uint32_t*)pl_raw;
        uint32_t i0 = pi[0], i1 = pi[1], i2 = pi[2], i3 = pi[3];
        bool lab[BATCH];
        bool int_mode = (i0 <= 1u) && (i1 <= 1u) && (i2 <= 1u) && (i3 <= 1u);
        bool flt_mode = !int_mode &&
            (i0 == 0u || i0 == 0x3F800000u) && (i1 == 0u || i1 == 0x3F800000u) &&
            (i2 == 0u || i2 == 0x3F800000u) && (i3 == 0u || i3 == 0x3F800000u);
        if (int_mode) {
            lab[0] = i0 != 0u; lab[1] = i1 != 0u; lab[2] = i2 != 0u; lab[3] = i3 != 0u;
        } else if (flt_mode) {
            lab[0] = i0 != 0u; lab[1] = i1 != 0u; lab[2] = i2 != 0u; lab[3] = i3 != 0u;
        } else {
            #pragma unroll
            for (int b = 0; b < BATCH; b++) lab[b] = pl_raw[b] != 0;
        }

        float loss = 0.f;
        #pragma unroll
        for (int b = 0; b < BATCH; b++) {
            float lp = pol[b] / cnt[b];
            float lr = ref[b] / cnt[b];
            float mult = lab[b] ? 1.f : -1.f;
            float z = 0.1f * (lp - lr) * mult;
            float s = 1.f / (1.f + expf(-z));
            loss += 1.f - s;
        }
        out[0] = loss / (float)BATCH;
    }
}

// ---------------------------------------------------------------------------
extern "C" void kernel_launch(void* const* d_in, const int* in_sizes, int n_in,
                              void* d_out, int out_size) {
    (void)in_sizes; (void)n_in; (void)out_size;
    const float*         x  = (const float*)d_in[0];
    const float*         rx = (const float*)d_in[1];
    const int*           y  = (const int*)d_in[2];
    const unsigned char* pl = (const unsigned char*)d_in[3];
    const float*         W  = (const float*)d_in[4];
    const float*         rW = (const float*)d_in[5];
    float* out = (float*)d_out;

    k_init<<<16, 256>>>();
    k_target<<<(2 * TOKENS * 32) / 256, 256>>>(x, rx, W, rW, y);
    dim3 grid(TOKENS / BM, VOCAB / BN, 2);   // M fastest -> W tile L2 reuse
    k_gemm<<<grid, 256>>>(x, rx, W, rW);
    k_final<<<1, 256>>>(y, pl, out);
}